// round 1
// baseline (speedup 1.0000x reference)
#include <cuda_runtime.h>

#define NN 50000
#define NE 800000
#define H_STEP 0.1f

// ---------------- scratch (device globals; no allocation allowed) ----------
static __device__ float4 g_xn[NN * 16];      // node state [n][64], node-major
static __device__ float4 g_y[NN * 16];       // y = KN[i] @ xn, [n][64]
static __device__ float4 g_div[NN * 16];     // scatter accumulator [n][64]
static __device__ float4 g_coords[NN];       // coords [n][3] (+pad)
static __device__ float4 g_Ai[NE * 16];      // edge features [e][64]
static __device__ float  g_w[NE];            // edge weights
static __device__ double g_sum[64];
static __device__ double g_sumsq[64];

__device__ __forceinline__ void red_add_v4(float4* addr, float4 v) {
    asm volatile("red.global.add.v4.f32 [%0], {%1,%2,%3,%4};"
                 :: "l"(addr), "f"(v.x), "f"(v.y), "f"(v.z), "f"(v.w)
                 : "memory");
}

// ---------------- N0: open projection + coords/XX0 + y(layer0) + zero div --
__global__ __launch_bounds__(128) void k_n0(
    const float* __restrict__ xn_in,      // [16][NN]
    const float* __restrict__ KNopen,     // [64][16]
    const float* __restrict__ KNclose,    // [3][64]
    const float* __restrict__ KN,         // [3][64][64]
    float* __restrict__ out_xx0)          // XX[0]: [3][NN]
{
    __shared__ float sOpenT[16 * 64];   // [f][o]
    __shared__ float sKN0T[64 * 64];    // [f][o]
    __shared__ float sCloseT[64 * 4];   // [f][c] (c padded to 4)
    int t = threadIdx.x;
    for (int idx = t; idx < 16 * 64; idx += 128) {
        int o = idx / 16, f = idx % 16;
        sOpenT[f * 64 + o] = KNopen[idx];
    }
    for (int idx = t; idx < 64 * 64; idx += 128) {
        int o = idx / 64, f = idx % 64;
        sKN0T[f * 64 + o] = KN[idx];            // KN[0]
    }
    for (int idx = t; idx < 64 * 4; idx += 128) {
        int f = idx / 4, c = idx % 4;
        sCloseT[idx] = (c < 3) ? KNclose[c * 64 + f] : 0.f;
    }
    if (blockIdx.x == 0 && t < 64) { g_sum[t] = 0.0; g_sumsq[t] = 0.0; }
    __syncthreads();

    int n = blockIdx.x * 128 + t;
    if (n >= NN) return;

    float x[64];
#pragma unroll
    for (int o = 0; o < 64; o++) x[o] = 0.f;
#pragma unroll
    for (int f = 0; f < 16; f++) {
        float xf = xn_in[f * NN + n];
#pragma unroll
        for (int o = 0; o < 64; o += 4) {
            float4 k = *(const float4*)&sOpenT[f * 64 + o];
            x[o]     += k.x * xf;
            x[o + 1] += k.y * xf;
            x[o + 2] += k.z * xf;
            x[o + 3] += k.w * xf;
        }
    }
    float4* xnrow  = &g_xn[n * 16];
    float4* divrow = &g_div[n * 16];
#pragma unroll
    for (int q = 0; q < 16; q++) {
        xnrow[q]  = make_float4(x[4 * q], x[4 * q + 1], x[4 * q + 2], x[4 * q + 3]);
        divrow[q] = make_float4(0.f, 0.f, 0.f, 0.f);
    }
    // coords = KNclose @ x
    float c0 = 0.f, c1 = 0.f, c2 = 0.f;
#pragma unroll
    for (int f = 0; f < 64; f++) {
        float4 kc = *(const float4*)&sCloseT[f * 4];
        c0 += kc.x * x[f]; c1 += kc.y * x[f]; c2 += kc.z * x[f];
    }
    g_coords[n] = make_float4(c0, c1, c2, 0.f);
    out_xx0[0 * NN + n] = c0;
    out_xx0[1 * NN + n] = c1;
    out_xx0[2 * NN + n] = c2;
    // y = KN[0] @ x  (chunked outputs)
#pragma unroll
    for (int oc = 0; oc < 4; oc++) {
        float acc[16];
#pragma unroll
        for (int q = 0; q < 16; q++) acc[q] = 0.f;
#pragma unroll
        for (int f = 0; f < 64; f++) {
            float xf = x[f];
#pragma unroll
            for (int q = 0; q < 16; q += 4) {
                float4 k = *(const float4*)&sKN0T[f * 64 + oc * 16 + q];
                acc[q]     += k.x * xf;
                acc[q + 1] += k.y * xf;
                acc[q + 2] += k.z * xf;
                acc[q + 3] += k.w * xf;
            }
        }
        float4* yrow = &g_y[n * 16 + oc * 4];
#pragma unroll
        for (int q = 0; q < 4; q++)
            yrow[q] = make_float4(acc[4 * q], acc[4 * q + 1], acc[4 * q + 2], acc[4 * q + 3]);
    }
}

// ---------------- E1: w + Ai = w*(y_i - y_j), accumulate sums --------------
__global__ __launch_bounds__(256) void k_e1(
    const int* __restrict__ iInd, const int* __restrict__ jInd)
{
    __shared__ float sSum[64], sSq[64];
    int t = threadIdx.x;
    if (t < 64) { sSum[t] = 0.f; sSq[t] = 0.f; }
    __syncthreads();

    int lane   = t & 15;
    int group  = blockIdx.x * 16 + (t >> 4);
    int stride = gridDim.x * 16;
    float s0 = 0.f, s1 = 0.f, s2 = 0.f, s3 = 0.f;
    float q0 = 0.f, q1 = 0.f, q2 = 0.f, q3 = 0.f;

    for (int e = group; e < NE; e += stride) {
        int i = iInd[e], j = jInd[e];
        float4 ci = g_coords[i], cj = g_coords[j];
        float dx = ci.x - cj.x, dy = ci.y - cj.y, dz = ci.z - cj.z;
        float w = __expf(-10.f * (dx * dx + dy * dy + dz * dz));
        if (lane == 0) g_w[e] = w;
        float4 yi = g_y[i * 16 + lane];
        float4 yj = g_y[j * 16 + lane];
        float4 a = make_float4(w * (yi.x - yj.x), w * (yi.y - yj.y),
                               w * (yi.z - yj.z), w * (yi.w - yj.w));
        g_Ai[e * 16 + lane] = a;
        s0 += a.x; s1 += a.y; s2 += a.z; s3 += a.w;
        q0 += a.x * a.x; q1 += a.y * a.y; q2 += a.z * a.z; q3 += a.w * a.w;
    }
    int c = lane * 4;
    atomicAdd(&sSum[c], s0);     atomicAdd(&sSum[c + 1], s1);
    atomicAdd(&sSum[c + 2], s2); atomicAdd(&sSum[c + 3], s3);
    atomicAdd(&sSq[c], q0);      atomicAdd(&sSq[c + 1], q1);
    atomicAdd(&sSq[c + 2], q2);  atomicAdd(&sSq[c + 3], q3);
    __syncthreads();
    if (t < 64)       atomicAdd(&g_sum[t], (double)sSum[t]);
    else if (t < 128) atomicAdd(&g_sumsq[t - 64], (double)sSq[t - 64]);
}

// ---------------- E2: normalize + relu + weighted scatter ------------------
template <bool STORE_X>
__global__ __launch_bounds__(256) void k_e2(
    const int* __restrict__ iInd, const int* __restrict__ jInd)
{
    int t    = threadIdx.x;
    int lane = t & 15;
    int c    = lane * 4;

    float mean[4], inv[4];
    const double invE = 1.0 / (double)NE;
#pragma unroll
    for (int d = 0; d < 4; d++) {
        double s  = g_sum[c + d];
        double sq = g_sumsq[c + d];
        double mu = s * invE;
        double var = sq * invE - mu * mu;
        mean[d] = (float)mu;
        inv[d]  = rsqrtf((float)var + 1e-5f);
    }

    int group  = blockIdx.x * 16 + (t >> 4);
    int stride = gridDim.x * 16;
    for (int e = group; e < NE; e += stride) {
        int i = iInd[e], j = jInd[e];
        float w = g_w[e];
        float4 a = g_Ai[e * 16 + lane];
        float4 x;
        x.x = fmaxf(0.f, (a.x - mean[0]) * inv[0]);
        x.y = fmaxf(0.f, (a.y - mean[1]) * inv[1]);
        x.z = fmaxf(0.f, (a.z - mean[2]) * inv[2]);
        x.w = fmaxf(0.f, (a.w - mean[3]) * inv[3]);
        if (STORE_X) g_Ai[e * 16 + lane] = x;
        float4 wg = make_float4(w * x.x, w * x.y, w * x.z, w * x.w);
        red_add_v4(&g_div[i * 16 + lane], wg);
        red_add_v4(&g_div[j * 16 + lane],
                   make_float4(-wg.x, -wg.y, -wg.z, -wg.w));
    }
}

// ---------------- Node update: xn -= H*K^T@div; coords/XX; y(next) ---------
__global__ __launch_bounds__(128) void k_node(
    const float* __restrict__ KNi,     // KN[i] [e][c]
    const float* __restrict__ KNnext,  // KN[i+1] or nullptr
    const float* __restrict__ KNclose,
    float* __restrict__ out_xx,        // XX[i+1]: [3][NN]
    float* __restrict__ out_xn,        // final xn out or nullptr
    int zero_sums)
{
    __shared__ float sK[64 * 64];     // KNi as-is [e*64+c]
    __shared__ float sKnT[64 * 64];   // KNnext^T [f*64+o]
    __shared__ float sCloseT[64 * 4];
    int t = threadIdx.x;
    for (int idx = t; idx < 4096; idx += 128) sK[idx] = KNi[idx];
    if (KNnext) {
        for (int idx = t; idx < 4096; idx += 128) {
            int o = idx / 64, f = idx % 64;
            sKnT[f * 64 + o] = KNnext[idx];
        }
    }
    for (int idx = t; idx < 256; idx += 128) {
        int f = idx / 4, cc = idx % 4;
        sCloseT[idx] = (cc < 3) ? KNclose[cc * 64 + f] : 0.f;
    }
    if (zero_sums && blockIdx.x == 0 && t < 64) { g_sum[t] = 0.0; g_sumsq[t] = 0.0; }
    __syncthreads();

    int n = blockIdx.x * 128 + t;
    if (n >= NN) return;

    float d[64];
    float4* divrow = &g_div[n * 16];
#pragma unroll
    for (int q = 0; q < 16; q++) {
        float4 v = divrow[q];
        d[4 * q] = v.x; d[4 * q + 1] = v.y; d[4 * q + 2] = v.z; d[4 * q + 3] = v.w;
        divrow[q] = make_float4(0.f, 0.f, 0.f, 0.f);   // ready for next layer
    }
    float4* xnrow = &g_xn[n * 16];
    // xn_new (chunked over 16 output channels at a time)
#pragma unroll
    for (int ch = 0; ch < 4; ch++) {
        float acc[16];
#pragma unroll
        for (int q = 0; q < 16; q++) acc[q] = 0.f;
#pragma unroll
        for (int e = 0; e < 64; e++) {
            float de = d[e];
#pragma unroll
            for (int q = 0; q < 16; q += 4) {
                float4 k = *(const float4*)&sK[e * 64 + ch * 16 + q];
                acc[q]     += k.x * de;
                acc[q + 1] += k.y * de;
                acc[q + 2] += k.z * de;
                acc[q + 3] += k.w * de;
            }
        }
#pragma unroll
        for (int q = 0; q < 4; q++) {
            float4 xv = xnrow[ch * 4 + q];
            xv.x -= H_STEP * acc[4 * q];
            xv.y -= H_STEP * acc[4 * q + 1];
            xv.z -= H_STEP * acc[4 * q + 2];
            xv.w -= H_STEP * acc[4 * q + 3];
            xnrow[ch * 4 + q] = xv;
        }
    }
    // reload full xn_new (same-thread RAW on global is safe)
    float x[64];
#pragma unroll
    for (int q = 0; q < 16; q++) {
        float4 v = xnrow[q];
        x[4 * q] = v.x; x[4 * q + 1] = v.y; x[4 * q + 2] = v.z; x[4 * q + 3] = v.w;
    }
    float c0 = 0.f, c1 = 0.f, c2 = 0.f;
#pragma unroll
    for (int f = 0; f < 64; f++) {
        float4 kc = *(const float4*)&sCloseT[f * 4];
        c0 += kc.x * x[f]; c1 += kc.y * x[f]; c2 += kc.z * x[f];
    }
    g_coords[n] = make_float4(c0, c1, c2, 0.f);
    out_xx[0 * NN + n] = c0;
    out_xx[1 * NN + n] = c1;
    out_xx[2 * NN + n] = c2;
    if (out_xn) {
        out_xn[0 * NN + n] = c0;
        out_xn[1 * NN + n] = c1;
        out_xn[2 * NN + n] = c2;
    }
    if (KNnext) {
#pragma unroll
        for (int oc = 0; oc < 4; oc++) {
            float acc[16];
#pragma unroll
            for (int q = 0; q < 16; q++) acc[q] = 0.f;
#pragma unroll
            for (int f = 0; f < 64; f++) {
                float xf = x[f];
#pragma unroll
                for (int q = 0; q < 16; q += 4) {
                    float4 k = *(const float4*)&sKnT[f * 64 + oc * 16 + q];
                    acc[q]     += k.x * xf;
                    acc[q + 1] += k.y * xf;
                    acc[q + 2] += k.z * xf;
                    acc[q + 3] += k.w * xf;
                }
            }
            float4* yrow = &g_y[n * 16 + oc * 4];
#pragma unroll
            for (int q = 0; q < 4; q++)
                yrow[q] = make_float4(acc[4 * q], acc[4 * q + 1],
                                      acc[4 * q + 2], acc[4 * q + 3]);
        }
    }
}

// ---------------- E3: xe_out = KEclose @ xe --------------------------------
__global__ __launch_bounds__(256) void k_e3(
    const float* __restrict__ KEclose, float* __restrict__ out_xe)
{
    __shared__ float sKT[64 * 16];   // [c][k]
    int t = threadIdx.x;
    for (int idx = t; idx < 1024; idx += 256) {
        int k = idx / 64, c = idx % 64;
        sKT[c * 16 + k] = KEclose[idx];
    }
    __syncthreads();
    int e = blockIdx.x * 256 + t;
    if (e >= NE) return;
    float acc[16];
#pragma unroll
    for (int k = 0; k < 16; k++) acc[k] = 0.f;
#pragma unroll
    for (int q = 0; q < 16; q++) {
        float4 xv = g_Ai[e * 16 + q];
        float xs[4] = {xv.x, xv.y, xv.z, xv.w};
#pragma unroll
        for (int dd = 0; dd < 4; dd++) {
            float xc = xs[dd];
            int c = 4 * q + dd;
#pragma unroll
            for (int kq = 0; kq < 4; kq++) {
                float4 kk = *(const float4*)&sKT[c * 16 + kq * 4];
                acc[kq * 4]     += kk.x * xc;
                acc[kq * 4 + 1] += kk.y * xc;
                acc[kq * 4 + 2] += kk.z * xc;
                acc[kq * 4 + 3] += kk.w * xc;
            }
        }
    }
#pragma unroll
    for (int k = 0; k < 16; k++) out_xe[k * NE + e] = acc[k];
}

// ---------------- launcher -------------------------------------------------
extern "C" void kernel_launch(void* const* d_in, const int* in_sizes, int n_in,
                              void* d_out, int out_size)
{
    const float* xn_in   = (const float*)d_in[0];
    // d_in[1] = xe input: dead (overwritten before first read in reference)
    const int*   iInd    = (const int*)d_in[2];
    const int*   jInd    = (const int*)d_in[3];
    const float* KNopen  = (const float*)d_in[4];
    // d_in[5] = KEopen: dead
    const float* KNclose = (const float*)d_in[6];
    const float* KEclose = (const float*)d_in[7];
    const float* KN      = (const float*)d_in[8];

    float* out    = (float*)d_out;
    float* out_xn = out;                       // [3][NN]
    float* out_xe = out + 3 * NN;              // [16][NE]
    float* out_XX = out + 3 * NN + 16 * NE;    // [4][3][NN]

    int nb_n  = (NN + 127) / 128;
    int nb_e3 = (NE + 255) / 256;
    const int GE = 1184;   // 8 blocks/SM on 148 SMs

    k_n0<<<nb_n, 128>>>(xn_in, KNopen, KNclose, KN, out_XX);
    for (int i = 0; i < 3; i++) {
        k_e1<<<GE, 256>>>(iInd, jInd);
        if (i < 2) k_e2<false><<<GE, 256>>>(iInd, jInd);
        else       k_e2<true ><<<GE, 256>>>(iInd, jInd);
        const float* KNi = KN + i * 4096;
        const float* KNn = (i < 2) ? (KN + (i + 1) * 4096) : nullptr;
        float* xx  = out_XX + (size_t)(i + 1) * 3 * NN;
        float* oxn = (i == 2) ? out_xn : nullptr;
        k_node<<<nb_n, 128>>>(KNi, KNn, KNclose, xx, oxn, (i < 2) ? 1 : 0);
    }
    k_e3<<<nb_e3, 256>>>(KEclose, out_xe);
}

// round 3
// speedup vs baseline: 1.0665x; 1.0665x over previous
#include <cuda_runtime.h>

#define NN 50000
#define NE 800000
#define H_STEP 0.1f

// ---------------- scratch (device globals; no allocation allowed) ----------
static __device__ float4 g_xn[NN * 16];      // node state [n][64], node-major
static __device__ float4 g_y[NN * 16];       // y = KN[i] @ xn, [n][64]
static __device__ float4 g_div[NN * 16];     // scatter accumulator [n][64]
static __device__ float4 g_coords[NN];       // coords [n][3] (+pad)
static __device__ float  g_w[NE];            // edge weights
static __device__ double g_sum[64];
static __device__ double g_sumsq[64];

__device__ __forceinline__ void red_add_v4(float4* addr, float4 v) {
    asm volatile("red.global.add.v4.f32 [%0], {%1,%2,%3,%4};"
                 :: "l"(addr), "f"(v.x), "f"(v.y), "f"(v.z), "f"(v.w)
                 : "memory");
}

// ---------------- N0: open projection + coords/XX0 + y(layer0) + zero div --
__global__ __launch_bounds__(128) void k_n0(
    const float* __restrict__ xn_in,      // [16][NN]
    const float* __restrict__ KNopen,     // [64][16]
    const float* __restrict__ KNclose,    // [3][64]
    const float* __restrict__ KN,         // [3][64][64]
    float* __restrict__ out_xx0)          // XX[0]: [3][NN]
{
    __shared__ float sOpenT[16 * 64];   // [f][o]
    __shared__ float sKN0T[64 * 64];    // [f][o]
    __shared__ float sCloseT[64 * 4];   // [f][c] (c padded to 4)
    int t = threadIdx.x;
    for (int idx = t; idx < 16 * 64; idx += 128) {
        int o = idx / 16, f = idx % 16;
        sOpenT[f * 64 + o] = KNopen[idx];
    }
    for (int idx = t; idx < 64 * 64; idx += 128) {
        int o = idx / 64, f = idx % 64;
        sKN0T[f * 64 + o] = KN[idx];            // KN[0]
    }
    for (int idx = t; idx < 64 * 4; idx += 128) {
        int f = idx / 4, c = idx % 4;
        sCloseT[idx] = (c < 3) ? KNclose[c * 64 + f] : 0.f;
    }
    if (blockIdx.x == 0 && t < 64) { g_sum[t] = 0.0; g_sumsq[t] = 0.0; }
    __syncthreads();

    int n = blockIdx.x * 128 + t;
    if (n >= NN) return;

    float x[64];
#pragma unroll
    for (int o = 0; o < 64; o++) x[o] = 0.f;
#pragma unroll
    for (int f = 0; f < 16; f++) {
        float xf = xn_in[f * NN + n];
#pragma unroll
        for (int o = 0; o < 64; o += 4) {
            float4 k = *(const float4*)&sOpenT[f * 64 + o];
            x[o]     += k.x * xf;
            x[o + 1] += k.y * xf;
            x[o + 2] += k.z * xf;
            x[o + 3] += k.w * xf;
        }
    }
    float4* xnrow  = &g_xn[n * 16];
    float4* divrow = &g_div[n * 16];
#pragma unroll
    for (int q = 0; q < 16; q++) {
        xnrow[q]  = make_float4(x[4 * q], x[4 * q + 1], x[4 * q + 2], x[4 * q + 3]);
        divrow[q] = make_float4(0.f, 0.f, 0.f, 0.f);
    }
    // coords = KNclose @ x
    float c0 = 0.f, c1 = 0.f, c2 = 0.f;
#pragma unroll
    for (int f = 0; f < 64; f++) {
        float4 kc = *(const float4*)&sCloseT[f * 4];
        c0 += kc.x * x[f]; c1 += kc.y * x[f]; c2 += kc.z * x[f];
    }
    g_coords[n] = make_float4(c0, c1, c2, 0.f);
    out_xx0[0 * NN + n] = c0;
    out_xx0[1 * NN + n] = c1;
    out_xx0[2 * NN + n] = c2;
    // y = KN[0] @ x  (chunked outputs)
#pragma unroll
    for (int oc = 0; oc < 4; oc++) {
        float acc[16];
#pragma unroll
        for (int q = 0; q < 16; q++) acc[q] = 0.f;
#pragma unroll
        for (int f = 0; f < 64; f++) {
            float xf = x[f];
#pragma unroll
            for (int q = 0; q < 16; q += 4) {
                float4 k = *(const float4*)&sKN0T[f * 64 + oc * 16 + q];
                acc[q]     += k.x * xf;
                acc[q + 1] += k.y * xf;
                acc[q + 2] += k.z * xf;
                acc[q + 3] += k.w * xf;
            }
        }
        float4* yrow = &g_y[n * 16 + oc * 4];
#pragma unroll
        for (int q = 0; q < 4; q++)
            yrow[q] = make_float4(acc[4 * q], acc[4 * q + 1], acc[4 * q + 2], acc[4 * q + 3]);
    }
}

// ---------------- E1: w + stats of a = w*(y_i - y_j) (no Ai store) ---------
__global__ __launch_bounds__(256) void k_e1(
    const int* __restrict__ iInd, const int* __restrict__ jInd)
{
    __shared__ float sSum[64], sSq[64];
    int t = threadIdx.x;
    if (t < 64) { sSum[t] = 0.f; sSq[t] = 0.f; }
    __syncthreads();

    int lane   = t & 15;
    int group  = blockIdx.x * 16 + (t >> 4);
    int stride = gridDim.x * 16;
    float s0 = 0.f, s1 = 0.f, s2 = 0.f, s3 = 0.f;
    float q0 = 0.f, q1 = 0.f, q2 = 0.f, q3 = 0.f;

    for (int e = group; e < NE; e += stride) {
        int i = iInd[e], j = jInd[e];
        float4 ci = g_coords[i], cj = g_coords[j];
        float dx = ci.x - cj.x, dy = ci.y - cj.y, dz = ci.z - cj.z;
        float w = __expf(-10.f * (dx * dx + dy * dy + dz * dz));
        if (lane == 0) g_w[e] = w;
        float4 yi = g_y[i * 16 + lane];
        float4 yj = g_y[j * 16 + lane];
        float4 a = make_float4(w * (yi.x - yj.x), w * (yi.y - yj.y),
                               w * (yi.z - yj.z), w * (yi.w - yj.w));
        s0 += a.x; s1 += a.y; s2 += a.z; s3 += a.w;
        q0 += a.x * a.x; q1 += a.y * a.y; q2 += a.z * a.z; q3 += a.w * a.w;
    }
    int c = lane * 4;
    atomicAdd(&sSum[c], s0);     atomicAdd(&sSum[c + 1], s1);
    atomicAdd(&sSum[c + 2], s2); atomicAdd(&sSum[c + 3], s3);
    atomicAdd(&sSq[c], q0);      atomicAdd(&sSq[c + 1], q1);
    atomicAdd(&sSq[c + 2], q2);  atomicAdd(&sSq[c + 3], q3);
    __syncthreads();
    if (t < 64)       atomicAdd(&g_sum[t], (double)sSum[t]);
    else if (t < 128) atomicAdd(&g_sumsq[t - 64], (double)sSq[t - 64]);
}

// ---------------- E2 (layers 0,1): recompute a, normalize+relu, scatter ----
__global__ __launch_bounds__(256) void k_e2(
    const int* __restrict__ iInd, const int* __restrict__ jInd)
{
    int t    = threadIdx.x;
    int lane = t & 15;
    int c    = lane * 4;

    float mean[4], inv[4];
    const double invE = 1.0 / (double)NE;
#pragma unroll
    for (int d = 0; d < 4; d++) {
        double s  = g_sum[c + d];
        double sq = g_sumsq[c + d];
        double mu = s * invE;
        double var = sq * invE - mu * mu;
        mean[d] = (float)mu;
        inv[d]  = rsqrtf((float)var + 1e-5f);
    }

    int group  = blockIdx.x * 16 + (t >> 4);
    int stride = gridDim.x * 16;
    for (int e = group; e < NE; e += stride) {
        int i = iInd[e], j = jInd[e];
        float w = g_w[e];
        float4 yi = g_y[i * 16 + lane];
        float4 yj = g_y[j * 16 + lane];
        float4 a = make_float4(w * (yi.x - yj.x), w * (yi.y - yj.y),
                               w * (yi.z - yj.z), w * (yi.w - yj.w));
        float4 x;
        x.x = fmaxf(0.f, (a.x - mean[0]) * inv[0]);
        x.y = fmaxf(0.f, (a.y - mean[1]) * inv[1]);
        x.z = fmaxf(0.f, (a.z - mean[2]) * inv[2]);
        x.w = fmaxf(0.f, (a.w - mean[3]) * inv[3]);
        float4 wg = make_float4(w * x.x, w * x.y, w * x.z, w * x.w);
        red_add_v4(&g_div[i * 16 + lane], wg);
        red_add_v4(&g_div[j * 16 + lane],
                   make_float4(-wg.x, -wg.y, -wg.z, -wg.w));
    }
}

// ---------------- E2 last layer: thread-per-edge, + fused xe_out = KEclose@x
__global__ __launch_bounds__(256) void k_e2_last(
    const int* __restrict__ iInd, const int* __restrict__ jInd,
    const float* __restrict__ KEclose,     // [16][64]
    float* __restrict__ out_xe)            // [16][NE]
{
    __shared__ float sKT[64 * 16];   // [c][k]
    __shared__ float sMean[64], sInv[64];
    int t = threadIdx.x;
    for (int idx = t; idx < 1024; idx += 256) {
        int k = idx / 64, c = idx % 64;
        sKT[c * 16 + k] = KEclose[idx];
    }
    if (t < 64) {
        const double invE = 1.0 / (double)NE;
        double s  = g_sum[t];
        double sq = g_sumsq[t];
        double mu = s * invE;
        double var = sq * invE - mu * mu;
        sMean[t] = (float)mu;
        sInv[t]  = rsqrtf((float)var + 1e-5f);
    }
    __syncthreads();

    int e = blockIdx.x * 256 + t;
    if (e >= NE) return;
    int i = iInd[e], j = jInd[e];
    float w = g_w[e];

    float acc[16];
#pragma unroll
    for (int k = 0; k < 16; k++) acc[k] = 0.f;

#pragma unroll
    for (int q = 0; q < 16; q++) {
        float4 yi = g_y[i * 16 + q];
        float4 yj = g_y[j * 16 + q];
        float4 mn = *(const float4*)&sMean[4 * q];
        float4 iv = *(const float4*)&sInv[4 * q];
        float4 x;
        x.x = fmaxf(0.f, (w * (yi.x - yj.x) - mn.x) * iv.x);
        x.y = fmaxf(0.f, (w * (yi.y - yj.y) - mn.y) * iv.y);
        x.z = fmaxf(0.f, (w * (yi.z - yj.z) - mn.z) * iv.z);
        x.w = fmaxf(0.f, (w * (yi.w - yj.w) - mn.w) * iv.w);
        float4 wg = make_float4(w * x.x, w * x.y, w * x.z, w * x.w);
        red_add_v4(&g_div[i * 16 + q], wg);
        red_add_v4(&g_div[j * 16 + q],
                   make_float4(-wg.x, -wg.y, -wg.z, -wg.w));
        float xs[4] = {x.x, x.y, x.z, x.w};
#pragma unroll
        for (int dd = 0; dd < 4; dd++) {
            float xc = xs[dd];
            int c = 4 * q + dd;
#pragma unroll
            for (int kq = 0; kq < 4; kq++) {
                float4 kk = *(const float4*)&sKT[c * 16 + kq * 4];
                acc[kq * 4]     += kk.x * xc;
                acc[kq * 4 + 1] += kk.y * xc;
                acc[kq * 4 + 2] += kk.z * xc;
                acc[kq * 4 + 3] += kk.w * xc;
            }
        }
    }
#pragma unroll
    for (int k = 0; k < 16; k++) out_xe[k * NE + e] = acc[k];
}

// ---------------- Node update: xn -= H*K^T@div; coords/XX; y(next) ---------
// Register-lean: input-chunked update matvec (acc[64] live, d consumed
// chunk-wise), x renames acc, then output-chunked y matvec.
__global__ void __launch_bounds__(128, 5) k_node(
    const float* __restrict__ KNi,     // KN[i] [e][c], used as-is
    const float* __restrict__ KNnext,  // KN[i+1] or nullptr
    const float* __restrict__ KNclose,
    float* __restrict__ out_xx,        // XX[i+1]: [3][NN]
    float* __restrict__ out_xn,        // final xn out or nullptr
    int zero_sums)
{
    __shared__ float sK[64 * 64];     // KNi as-is: sK[e*64+c]
    __shared__ float sKnT[64 * 64];   // KNnext^T: [f*64+o]
    __shared__ float sCloseT[64 * 4];
    int t = threadIdx.x;
    for (int idx = t; idx < 4096; idx += 128) sK[idx] = KNi[idx];
    if (KNnext) {
        for (int idx = t; idx < 4096; idx += 128) {
            int o = idx / 64, f = idx % 64;
            sKnT[f * 64 + o] = KNnext[idx];
        }
    }
    for (int idx = t; idx < 256; idx += 128) {
        int f = idx / 4, cc = idx % 4;
        sCloseT[idx] = (cc < 3) ? KNclose[cc * 64 + f] : 0.f;
    }
    if (zero_sums && blockIdx.x == 0 && t < 64) { g_sum[t] = 0.0; g_sumsq[t] = 0.0; }
    __syncthreads();

    int n = blockIdx.x * 128 + t;
    if (n >= NN) return;

    float4* divrow = &g_div[n * 16];
    float4* xnrow  = &g_xn[n * 16];

    // acc[c] = sum_e KNi[e][c] * d[e], input-chunked (4 inputs at a time)
    float acc[64];
#pragma unroll
    for (int c = 0; c < 64; c++) acc[c] = 0.f;
#pragma unroll
    for (int q = 0; q < 16; q++) {
        float4 dv = divrow[q];
        divrow[q] = make_float4(0.f, 0.f, 0.f, 0.f);   // ready for next layer
        float ds[4] = {dv.x, dv.y, dv.z, dv.w};
#pragma unroll
        for (int ee = 0; ee < 4; ee++) {
            float de = ds[ee];
            const float* krow = &sK[(4 * q + ee) * 64];
#pragma unroll
            for (int c = 0; c < 64; c += 4) {
                float4 k = *(const float4*)&krow[c];
                acc[c]     += k.x * de;
                acc[c + 1] += k.y * de;
                acc[c + 2] += k.z * de;
                acc[c + 3] += k.w * de;
            }
        }
    }
    // x = xn - H*acc  (reuse acc registers as x), store back
#pragma unroll
    for (int q = 0; q < 16; q++) {
        float4 xv = xnrow[q];
        acc[4 * q]     = xv.x - H_STEP * acc[4 * q];
        acc[4 * q + 1] = xv.y - H_STEP * acc[4 * q + 1];
        acc[4 * q + 2] = xv.z - H_STEP * acc[4 * q + 2];
        acc[4 * q + 3] = xv.w - H_STEP * acc[4 * q + 3];
        xnrow[q] = make_float4(acc[4 * q], acc[4 * q + 1],
                               acc[4 * q + 2], acc[4 * q + 3]);
    }
    // coords
    float c0 = 0.f, c1 = 0.f, c2 = 0.f;
#pragma unroll
    for (int f = 0; f < 64; f++) {
        float4 kc = *(const float4*)&sCloseT[f * 4];
        c0 += kc.x * acc[f]; c1 += kc.y * acc[f]; c2 += kc.z * acc[f];
    }
    g_coords[n] = make_float4(c0, c1, c2, 0.f);
    out_xx[0 * NN + n] = c0;
    out_xx[1 * NN + n] = c1;
    out_xx[2 * NN + n] = c2;
    if (out_xn) {
        out_xn[0 * NN + n] = c0;
        out_xn[1 * NN + n] = c1;
        out_xn[2 * NN + n] = c2;
    }
    // y = KNnext @ x, output-chunked (16 outputs at a time)
    if (KNnext) {
#pragma unroll
        for (int oc = 0; oc < 4; oc++) {
            float yacc[16];
#pragma unroll
            for (int q = 0; q < 16; q++) yacc[q] = 0.f;
#pragma unroll
            for (int f = 0; f < 64; f++) {
                float xf = acc[f];
#pragma unroll
                for (int q = 0; q < 16; q += 4) {
                    float4 k = *(const float4*)&sKnT[f * 64 + oc * 16 + q];
                    yacc[q]     += k.x * xf;
                    yacc[q + 1] += k.y * xf;
                    yacc[q + 2] += k.z * xf;
                    yacc[q + 3] += k.w * xf;
                }
            }
            float4* yrow = &g_y[n * 16 + oc * 4];
#pragma unroll
            for (int q = 0; q < 4; q++)
                yrow[q] = make_float4(yacc[4 * q], yacc[4 * q + 1],
                                      yacc[4 * q + 2], yacc[4 * q + 3]);
        }
    }
}

// ---------------- launcher -------------------------------------------------
extern "C" void kernel_launch(void* const* d_in, const int* in_sizes, int n_in,
                              void* d_out, int out_size)
{
    const float* xn_in   = (const float*)d_in[0];
    // d_in[1] = xe input: dead (overwritten before first read in reference)
    const int*   iInd    = (const int*)d_in[2];
    const int*   jInd    = (const int*)d_in[3];
    const float* KNopen  = (const float*)d_in[4];
    // d_in[5] = KEopen: dead
    const float* KNclose = (const float*)d_in[6];
    const float* KEclose = (const float*)d_in[7];
    const float* KN      = (const float*)d_in[8];

    float* out    = (float*)d_out;
    float* out_xn = out;                       // [3][NN]
    float* out_xe = out + 3 * NN;              // [16][NE]
    float* out_XX = out + 3 * NN + 16 * NE;    // [4][3][NN]

    int nb_n  = (NN + 127) / 128;
    int nb_el = (NE + 255) / 256;
    const int GE = 1184;

    k_n0<<<nb_n, 128>>>(xn_in, KNopen, KNclose, KN, out_XX);
    for (int i = 0; i < 3; i++) {
        k_e1<<<GE, 256>>>(iInd, jInd);
        if (i < 2) k_e2<<<GE, 256>>>(iInd, jInd);
        else       k_e2_last<<<nb_el, 256>>>(iInd, jInd, KEclose, out_xe);
        const float* KNi = KN + i * 4096;
        const float* KNn = (i < 2) ? (KN + (i + 1) * 4096) : nullptr;
        float* xx  = out_XX + (size_t)(i + 1) * 3 * NN;
        float* oxn = (i == 2) ? out_xn : nullptr;
        k_node<<<nb_n, 128>>>(KNi, KNn, KNclose, xx, oxn, (i < 2) ? 1 : 0);
    }
}